// round 7
// baseline (speedup 1.0000x reference)
#include <cuda_runtime.h>
#include <cuda_fp16.h>
#include <cstdint>

#define N_EXPERTS 8
#define FDIM1 1024
#define FDIM2 512
#define NCLS 64
#define BATCH 16384
#define APITCH 40   // smem row pitch in fp16 elems (32 + 8 pad: conflict-free ldmatrix)

// ---------------- scratch (static device arrays; allocation-free) ----------
__device__ __align__(16) __half g_W1t[N_EXPERTS * FDIM2 * FDIM1];
__device__ __align__(16) __half g_W2t[N_EXPERTS * NCLS * FDIM2];
__device__ __align__(16) __half g_X16[(size_t)BATCH * FDIM1];
__device__ __align__(16) __half g_H[(size_t)BATCH * FDIM2];
__device__ int g_idx[N_EXPERTS * BATCH];
__device__ int g_cnt[N_EXPERTS];

// ---------------- helpers ---------------------------------------------------
__device__ __forceinline__ uint32_t smem_u32(const void* p) {
    uint32_t a;
    asm("{ .reg .u64 t; cvta.to.shared.u64 t, %1; cvt.u32.u64 %0, t; }"
        : "=r"(a) : "l"(p));
    return a;
}

__device__ __forceinline__ void ldsm4(uint32_t& r0, uint32_t& r1, uint32_t& r2,
                                      uint32_t& r3, uint32_t addr) {
    asm volatile("ldmatrix.sync.aligned.m8n8.x4.shared.b16 {%0,%1,%2,%3}, [%4];"
                 : "=r"(r0), "=r"(r1), "=r"(r2), "=r"(r3) : "r"(addr));
}

__device__ __forceinline__ void mma_fp16(float* c, const uint32_t* a,
                                         uint32_t b0, uint32_t b1) {
    asm volatile(
        "mma.sync.aligned.m16n8k16.row.col.f32.f16.f16.f32 "
        "{%0,%1,%2,%3}, {%4,%5,%6,%7}, {%8,%9}, {%0,%1,%2,%3};"
        : "+f"(c[0]), "+f"(c[1]), "+f"(c[2]), "+f"(c[3])
        : "r"(a[0]), "r"(a[1]), "r"(a[2]), "r"(a[3]), "r"(b0), "r"(b1));
}

__device__ __forceinline__ void cpasync16(uint32_t dst, const void* src) {
    asm volatile("cp.async.ca.shared.global [%0], [%1], 16;"
                 :: "r"(dst), "l"(src) : "memory");
}
__device__ __forceinline__ void cpasync16z(uint32_t dst, const void* src, int sz) {
    asm volatile("cp.async.ca.shared.global [%0], [%1], 16, %2;"
                 :: "r"(dst), "l"(src), "r"(sz) : "memory");
}
#define CP_COMMIT() asm volatile("cp.async.commit_group;" ::: "memory")
#define CP_WAIT(n) asm volatile("cp.async.wait_group %0;" ::"n"(n) : "memory")

__device__ __forceinline__ uint32_t packh2(float v0, float v1) {
    __half2 h = __floats2half2_rn(v0, v1);
    return *(uint32_t*)&h;
}

// ---------------- small kernels ---------------------------------------------
__global__ void k_reset() {
    if (threadIdx.x < N_EXPERTS) g_cnt[threadIdx.x] = 0;
}

__global__ void k_bucket(const int* __restrict__ domain) {
    int i = blockIdx.x * blockDim.x + threadIdx.x;
    if (i < BATCH) {
        int e = domain[i];
        int p = atomicAdd(&g_cnt[e], 1);
        g_idx[e * BATCH + p] = i;
    }
}

// Convert x fp32 -> fp16 (no transpose)
__global__ void k_convX(const float* __restrict__ src) {
    size_t i = ((size_t)blockIdx.x * blockDim.x + threadIdx.x) * 8;
    float4 a = *(const float4*)(src + i);
    float4 b = *(const float4*)(src + i + 4);
    uint4 o = make_uint4(packh2(a.x, a.y), packh2(a.z, a.w),
                         packh2(b.x, b.y), packh2(b.z, b.w));
    *(uint4*)(&g_X16[i]) = o;
}

// Transpose+convert W1 [e][k=1024][n=512] fp32 -> [e][n][k] fp16
__global__ void k_convW1(const float* __restrict__ src) {
    __shared__ float tile[32][33];
    int e = blockIdx.z;
    int kb = blockIdx.x * 32, nb = blockIdx.y * 32;
    const float* s = src + ((size_t)e * FDIM1 + kb) * FDIM2 + nb;
    int tx = threadIdx.x, ty = threadIdx.y;
#pragma unroll
    for (int i = 0; i < 32; i += 8) tile[ty + i][tx] = s[(size_t)(ty + i) * FDIM2 + tx];
    __syncthreads();
    size_t ob = ((size_t)e * FDIM2 + nb) * FDIM1 + kb;
#pragma unroll
    for (int i = 0; i < 32; i += 8)
        g_W1t[ob + (size_t)(ty + i) * FDIM1 + tx] = __float2half_rn(tile[tx][ty + i]);
}

// Transpose+convert W2 [e][k=512][n=64] fp32 -> [e][n][k] fp16
__global__ void k_convW2(const float* __restrict__ src) {
    __shared__ float tile[32][33];
    int e = blockIdx.z;
    int kb = blockIdx.x * 32, nb = blockIdx.y * 32;
    const float* s = src + ((size_t)e * FDIM2 + kb) * NCLS + nb;
    int tx = threadIdx.x, ty = threadIdx.y;
#pragma unroll
    for (int i = 0; i < 32; i += 8) tile[ty + i][tx] = s[(size_t)(ty + i) * NCLS + tx];
    __syncthreads();
    size_t ob = ((size_t)e * NCLS + nb) * FDIM2 + kb;
#pragma unroll
    for (int i = 0; i < 32; i += 8)
        g_W2t[ob + (size_t)(ty + i) * FDIM2 + tx] = __float2half_rn(tile[tx][ty + i]);
}

// ---------------- layer 1: fp16 mma.sync GEMM, 3-stage cp.async -------------
// CTA: 128 rows x 128 cols, K=1024 in 32 chunks of 32. 8 warps = 2(M) x 4(N).
// Dynamic smem layout (bytes):
//   [0,512)    int rows[128]
//   [512,1024) float bias[128]
//   [1024,...) 3 stages x { A 10240 | B 10240 }
#define L1_ROWS 0
#define L1_BIAS 512
#define L1_BASE 1024
#define L1_ASTG 10240
#define L1_STG 20480
#define L1_SMEM (1024 + 3 * L1_STG)

__global__ __launch_bounds__(256, 2) void k_gemm1(const float* __restrict__ b1)
{
    const int e = blockIdx.z;
    const int cnt = g_cnt[e];
    const int mbase = blockIdx.x * 128;
    if (mbase >= cnt) return;
    const int nbase = blockIdx.y * 128;

    extern __shared__ __align__(16) char sm1[];
    int* rows = (int*)(sm1 + L1_ROWS);
    float* bias = (float*)(sm1 + L1_BIAS);
    const uint32_t sb = smem_u32(sm1);

    const int t = threadIdx.x;
    if (t < 128) {
        int p = mbase + t;
        rows[t] = (p < cnt) ? g_idx[e * BATCH + p] : -1;
        bias[t] = b1[e * FDIM2 + nbase + t];
    }
    __syncthreads();

    // ---- load mappings: thread -> (row lr, 16-half segment seg)
    const int lr = t >> 1;
    const int seg = t & 1;
    const __half* xsrc;
    int xsz;
    {
        int r = rows[lr];
        xsrc = (r >= 0) ? g_X16 + (size_t)r * FDIM1 + seg * 16 : g_X16;
        xsz = (r >= 0) ? 16 : 0;
    }
    const __half* wsrc = g_W1t + (size_t)(e * FDIM2 + nbase + lr) * FDIM1 + seg * 16;
    const uint32_t sOffT = lr * (APITCH * 2) + seg * 32;

#define L1_ISSUE(kc, stg)                                                  \
    do {                                                                   \
        uint32_t ba = sb + L1_BASE + (stg) * L1_STG;                       \
        cpasync16z(ba + sOffT,      xsrc + (kc), xsz);                     \
        cpasync16z(ba + sOffT + 16, xsrc + (kc) + 8, xsz);                 \
        cpasync16(ba + L1_ASTG + sOffT,      wsrc + (kc));                 \
        cpasync16(ba + L1_ASTG + sOffT + 16, wsrc + (kc) + 8);             \
        CP_COMMIT();                                                       \
    } while (0)

    const int l = t & 31, wid = t >> 5;
    const int wm = (wid >> 2) * 64, wn = (wid & 3) * 32;
    const int lrow = l & 15;
    const int lk = (l >> 4) * 8;

    float acc[4][4][4];
#pragma unroll
    for (int i = 0; i < 4; i++)
#pragma unroll
        for (int j = 0; j < 4; j++)
#pragma unroll
            for (int q = 0; q < 4; q++) acc[i][j][q] = 0.f;

    // prologue: stages 0,1 in flight
    L1_ISSUE(0, 0);
    L1_ISSUE(32, 1);

    int stg = 0;
    for (int c = 0; c < 32; c++) {
        if (c + 2 < 32) {
            int s2 = stg + 2;
            if (s2 >= 3) s2 -= 3;
            L1_ISSUE((c + 2) * 32, s2);
        } else {
            CP_COMMIT();  // keep group arithmetic uniform
        }
        CP_WAIT(2);       // group c has landed
        __syncthreads();

        const uint32_t aA = sb + L1_BASE + stg * L1_STG;
        const uint32_t aB = aA + L1_ASTG;
#pragma unroll
        for (int ks = 0; ks < 32; ks += 16) {
            uint32_t ah[4][4], bh[4][2];
#pragma unroll
            for (int mt = 0; mt < 4; mt++) {
                uint32_t off = ((wm + mt * 16 + lrow) * APITCH + ks + lk) * 2;
                ldsm4(ah[mt][0], ah[mt][1], ah[mt][2], ah[mt][3], aA + off);
            }
#pragma unroll
            for (int bg = 0; bg < 2; bg++) {
                uint32_t off = ((wn + bg * 16 + lrow) * APITCH + ks + lk) * 2;
                uint32_t r0, r1, r2, r3;
                ldsm4(r0, r1, r2, r3, aB + off);
                bh[2 * bg][0] = r0; bh[2 * bg + 1][0] = r1;
                bh[2 * bg][1] = r2; bh[2 * bg + 1][1] = r3;
            }
#pragma unroll
            for (int mt = 0; mt < 4; mt++)
#pragma unroll
                for (int nt = 0; nt < 4; nt++)
                    mma_fp16(acc[mt][nt], ah[mt], bh[nt][0], bh[nt][1]);
        }
        __syncthreads();  // stage stg free for reuse
        if (++stg == 3) stg = 0;
    }

    // epilogue: + bias, relu, fp16, scatter to g_H
#pragma unroll
    for (int mt = 0; mt < 4; mt++) {
        int r0i = wm + mt * 16 + (l >> 2);
        int ra = rows[r0i], rb = rows[r0i + 8];
#pragma unroll
        for (int nt = 0; nt < 4; nt++) {
            int cl = wn + nt * 8 + (l & 3) * 2;
            float b0 = bias[cl], b1v = bias[cl + 1];
            if (ra >= 0) {
                uint32_t h = packh2(fmaxf(acc[mt][nt][0] + b0, 0.f),
                                    fmaxf(acc[mt][nt][1] + b1v, 0.f));
                *(uint32_t*)(&g_H[(size_t)ra * FDIM2 + nbase + cl]) = h;
            }
            if (rb >= 0) {
                uint32_t h = packh2(fmaxf(acc[mt][nt][2] + b0, 0.f),
                                    fmaxf(acc[mt][nt][3] + b1v, 0.f));
                *(uint32_t*)(&g_H[(size_t)rb * FDIM2 + nbase + cl]) = h;
            }
        }
    }
#undef L1_ISSUE
}

// ---------------- layer 2: fp16 mma.sync GEMM + softmax ---------------------
// CTA: 128 rows x 64 cols, K=512 in 16 chunks of 32. 8 warps = 4(M) x 2(N).
#define SM2_A 0
#define SM2_B 10240
#define SM2_SZ 34816  /* union with logits: 128 x 68 floats */

__global__ __launch_bounds__(256) void k_gemm2(
    const float* __restrict__ b2, float* __restrict__ out)
{
    const int e = blockIdx.y;
    const int cnt = g_cnt[e];
    const int mbase = blockIdx.x * 128;
    if (mbase >= cnt) return;

    __shared__ int rows[128];
    __shared__ float b2s[64];
    __shared__ __align__(16) char sm[SM2_SZ];

    const int t = threadIdx.x;
    if (t < 128) {
        int p = mbase + t;
        rows[t] = (p < cnt) ? g_idx[e * BATCH + p] : -1;
    }
    if (t < 64) b2s[t] = b2[e * NCLS + t];
    __syncthreads();

    __half* sA = (__half*)(sm + SM2_A);
    __half* sB = (__half*)(sm + SM2_B);

    const int lr = t >> 1;
    const int lo16 = (t & 1) * 16;
    const int hr = rows[lr];
    const __half* hp = (hr >= 0) ? g_H + (size_t)hr * FDIM2 + lo16 : nullptr;
    const int br = t >> 2, blo8 = (t & 3) * 8;
    const __half* wp = g_W2t + (size_t)(e * NCLS + br) * FDIM2 + blo8;

    uint4 ha[2], wb;

#define L2_LOAD(kc)                                                       \
    do {                                                                  \
        if (hp) {                                                         \
            ha[0] = *(const uint4*)(hp + (kc));                           \
            ha[1] = *(const uint4*)(hp + (kc) + 8);                       \
        } else {                                                          \
            ha[0] = ha[1] = make_uint4(0, 0, 0, 0);                       \
        }                                                                 \
        wb = *(const uint4*)(wp + (kc));                                  \
    } while (0)

    const int l = t & 31, wid = t >> 5;
    const int wm = (wid >> 1) * 32, wn = (wid & 1) * 32;
    const uint32_t aA = smem_u32(sA);
    const uint32_t aB = smem_u32(sB);
    const int lrow = l & 15;
    const int lk = (l >> 4) * 8;

    float acc[2][4][4];
#pragma unroll
    for (int i = 0; i < 2; i++)
#pragma unroll
        for (int j = 0; j < 4; j++)
#pragma unroll
            for (int q = 0; q < 4; q++) acc[i][j][q] = 0.f;

    L2_LOAD(0);

    for (int c = 0; c < 16; c++) {
        __syncthreads();
        *(uint4*)(&sA[lr * APITCH + lo16])      = ha[0];
        *(uint4*)(&sA[lr * APITCH + lo16 + 8])  = ha[1];
        *(uint4*)(&sB[br * APITCH + blo8])      = wb;
        __syncthreads();
        if (c < 15) L2_LOAD((c + 1) * 32);

#pragma unroll
        for (int ks = 0; ks < 32; ks += 16) {
            uint32_t ah[2][4], bh[4][2];
#pragma unroll
            for (int mt = 0; mt < 2; mt++) {
                uint32_t off = ((wm + mt * 16 + lrow) * APITCH + ks + lk) * 2;
                ldsm4(ah[mt][0], ah[mt][1], ah[mt][2], ah[mt][3], aA + off);
            }
#pragma unroll
            for (int bg = 0; bg < 2; bg++) {
                uint32_t off = ((wn + bg * 16 + lrow) * APITCH + ks + lk) * 2;
                uint32_t r0, r1, r2, r3;
                ldsm4(r0, r1, r2, r3, aB + off);
                bh[2 * bg][0] = r0; bh[2 * bg + 1][0] = r1;
                bh[2 * bg][1] = r2; bh[2 * bg + 1][1] = r3;
            }
#pragma unroll
            for (int mt = 0; mt < 2; mt++)
#pragma unroll
                for (int nt = 0; nt < 4; nt++)
                    mma_fp16(acc[mt][nt], ah[mt], bh[nt][0], bh[nt][1]);
        }
    }

    // logits -> smem (union over A/B buffers), then per-thread softmax
    __syncthreads();
    float* lg = (float*)sm;  // [128][68]
#pragma unroll
    for (int mt = 0; mt < 2; mt++) {
        int r0i = wm + mt * 16 + (l >> 2);
#pragma unroll
        for (int nt = 0; nt < 4; nt++) {
            int cl = wn + nt * 8 + (l & 3) * 2;
            lg[r0i * 68 + cl]           = acc[mt][nt][0];
            lg[r0i * 68 + cl + 1]       = acc[mt][nt][1];
            lg[(r0i + 8) * 68 + cl]     = acc[mt][nt][2];
            lg[(r0i + 8) * 68 + cl + 1] = acc[mt][nt][3];
        }
    }
    __syncthreads();

    if (t < 128) {
        int r = rows[t];
        if (r >= 0) {
            float v[64];
            float mx = -3.4e38f;
#pragma unroll
            for (int j = 0; j < 64; j++) {
                v[j] = lg[t * 68 + j] + b2s[j];
                mx = fmaxf(mx, v[j]);
            }
            float s = 0.f;
#pragma unroll
            for (int j = 0; j < 64; j++) {
                v[j] = __expf(v[j] - mx);
                s += v[j];
            }
            float inv = 1.0f / s;
            float4* op = (float4*)(out + (size_t)r * NCLS);
#pragma unroll
            for (int q = 0; q < 16; q++)
                op[q] = make_float4(v[4 * q] * inv, v[4 * q + 1] * inv,
                                    v[4 * q + 2] * inv, v[4 * q + 3] * inv);
        }
    }
#undef L2_LOAD
}

// ---------------------------------------------------------------------------
extern "C" void kernel_launch(void* const* d_in, const int* in_sizes, int n_in,
                              void* d_out, int out_size)
{
    const int*   domain = (const int*)  d_in[0];
    const float* x      = (const float*)d_in[1];
    const float* W1     = (const float*)d_in[2];
    const float* b1     = (const float*)d_in[3];
    const float* W2     = (const float*)d_in[4];
    const float* b2     = (const float*)d_in[5];
    float* out = (float*)d_out;

    cudaFuncSetAttribute(k_gemm1, cudaFuncAttributeMaxDynamicSharedMemorySize, L1_SMEM);

    k_reset<<<1, 32>>>();
    k_bucket<<<BATCH / 256, 256>>>(domain);
    k_convX<<<(BATCH * FDIM1 / 8) / 256, 256>>>(x);
    k_convW1<<<dim3(FDIM1 / 32, FDIM2 / 32, N_EXPERTS), dim3(32, 8)>>>(W1);
    k_convW2<<<dim3(FDIM2 / 32, NCLS / 32, N_EXPERTS), dim3(32, 8)>>>(W2);
    k_gemm1<<<dim3(BATCH / 128, FDIM2 / 128, N_EXPERTS), 256, L1_SMEM>>>(b1);
    k_gemm2<<<dim3(BATCH / 128, N_EXPERTS), 256>>>(b2, out);
}

// round 8
// speedup vs baseline: 1.3967x; 1.3967x over previous
#include <cuda_runtime.h>
#include <cuda_fp16.h>
#include <cstdint>

#define N_EXPERTS 8
#define FDIM1 1024
#define FDIM2 512
#define NCLS 64
#define BATCH 16384
#define APITCH 40   // smem row pitch in fp16 elems (32 + 8 pad: conflict-free ldmatrix)

// ---------------- scratch (static device arrays; allocation-free) ----------
__device__ __align__(16) __half g_W1t[N_EXPERTS * FDIM2 * FDIM1];
__device__ __align__(16) __half g_W2t[N_EXPERTS * NCLS * FDIM2];
__device__ __align__(16) __half g_X16[(size_t)BATCH * FDIM1];
__device__ __align__(16) __half g_H[(size_t)BATCH * FDIM2];
__device__ int g_idx[N_EXPERTS * BATCH];
__device__ int g_cnt[N_EXPERTS];

// ---------------- helpers ---------------------------------------------------
__device__ __forceinline__ uint32_t smem_u32(const void* p) {
    uint32_t a;
    asm("{ .reg .u64 t; cvta.to.shared.u64 t, %1; cvt.u32.u64 %0, t; }"
        : "=r"(a) : "l"(p));
    return a;
}

__device__ __forceinline__ void ldsm4(uint32_t& r0, uint32_t& r1, uint32_t& r2,
                                      uint32_t& r3, uint32_t addr) {
    asm volatile("ldmatrix.sync.aligned.m8n8.x4.shared.b16 {%0,%1,%2,%3}, [%4];"
                 : "=r"(r0), "=r"(r1), "=r"(r2), "=r"(r3) : "r"(addr));
}

__device__ __forceinline__ void mma_fp16(float* c, const uint32_t* a,
                                         uint32_t b0, uint32_t b1) {
    asm volatile(
        "mma.sync.aligned.m16n8k16.row.col.f32.f16.f16.f32 "
        "{%0,%1,%2,%3}, {%4,%5,%6,%7}, {%8,%9}, {%0,%1,%2,%3};"
        : "+f"(c[0]), "+f"(c[1]), "+f"(c[2]), "+f"(c[3])
        : "r"(a[0]), "r"(a[1]), "r"(a[2]), "r"(a[3]), "r"(b0), "r"(b1));
}

__device__ __forceinline__ void cpasync16(uint32_t dst, const void* src) {
    asm volatile("cp.async.ca.shared.global [%0], [%1], 16;"
                 :: "r"(dst), "l"(src) : "memory");
}
#define CP_COMMIT() asm volatile("cp.async.commit_group;" ::: "memory")
#define CP_WAIT(n) asm volatile("cp.async.wait_group %0;" ::"n"(n) : "memory")

__device__ __forceinline__ uint32_t packh2(float v0, float v1) {
    __half2 h = __floats2half2_rn(v0, v1);
    return *(uint32_t*)&h;
}

// ---------------- small kernels ---------------------------------------------
__global__ void k_reset() {
    if (threadIdx.x < N_EXPERTS) g_cnt[threadIdx.x] = 0;
}

__global__ void k_bucket(const int* __restrict__ domain) {
    int i = blockIdx.x * blockDim.x + threadIdx.x;
    if (i < BATCH) {
        int e = domain[i];
        int p = atomicAdd(&g_cnt[e], 1);
        g_idx[e * BATCH + p] = i;
    }
}

// Convert x fp32 -> fp16 (no transpose)
__global__ void k_convX(const float* __restrict__ src) {
    size_t i = ((size_t)blockIdx.x * blockDim.x + threadIdx.x) * 8;
    float4 a = *(const float4*)(src + i);
    float4 b = *(const float4*)(src + i + 4);
    uint4 o = make_uint4(packh2(a.x, a.y), packh2(a.z, a.w),
                         packh2(b.x, b.y), packh2(b.z, b.w));
    *(uint4*)(&g_X16[i]) = o;
}

// Transpose+convert W1 [e][k=1024][n=512] fp32 -> [e][n][k] fp16
__global__ void k_convW1(const float* __restrict__ src) {
    __shared__ float tile[32][33];
    int e = blockIdx.z;
    int kb = blockIdx.x * 32, nb = blockIdx.y * 32;
    const float* s = src + ((size_t)e * FDIM1 + kb) * FDIM2 + nb;
    int tx = threadIdx.x, ty = threadIdx.y;
#pragma unroll
    for (int i = 0; i < 32; i += 8) tile[ty + i][tx] = s[(size_t)(ty + i) * FDIM2 + tx];
    __syncthreads();
    size_t ob = ((size_t)e * FDIM2 + nb) * FDIM1 + kb;
#pragma unroll
    for (int i = 0; i < 32; i += 8)
        g_W1t[ob + (size_t)(ty + i) * FDIM1 + tx] = __float2half_rn(tile[tx][ty + i]);
}

// Transpose+convert W2 [e][k=512][n=64] fp32 -> [e][n][k] fp16
__global__ void k_convW2(const float* __restrict__ src) {
    __shared__ float tile[32][33];
    int e = blockIdx.z;
    int kb = blockIdx.x * 32, nb = blockIdx.y * 32;
    const float* s = src + ((size_t)e * FDIM2 + kb) * NCLS + nb;
    int tx = threadIdx.x, ty = threadIdx.y;
#pragma unroll
    for (int i = 0; i < 32; i += 8) tile[ty + i][tx] = s[(size_t)(ty + i) * NCLS + tx];
    __syncthreads();
    size_t ob = ((size_t)e * NCLS + nb) * FDIM2 + kb;
#pragma unroll
    for (int i = 0; i < 32; i += 8)
        g_W2t[ob + (size_t)(ty + i) * FDIM2 + tx] = __float2half_rn(tile[tx][ty + i]);
}

// ---------------- layer 1: fp16 mma.sync GEMM (R6 pipeline, fp16 A) ---------
// CTA: 128 rows x 128 cols, K=1024 in 32 chunks of 32. 8 warps = 2(M) x 4(N).
// 2-stage double buffer; B via cp.async + wait(1), A via LDG regs -> STS.
// Dynamic smem layout (bytes):
//   [0,512)        int rows[128]
//   [512,1024)     float bias[128]
//   [1024,21504)   sA[2][128*APITCH] halfs (10240 B/stage)
//   [21504,41984)  sB[2][...]
#define L1_ROWS 0
#define L1_BIAS 512
#define L1_A 1024
#define L1_B 21504
#define L1_STG 10240
#define L1_SMEM 41984

__global__ __launch_bounds__(256, 2) void k_gemm1(const float* __restrict__ b1)
{
    const int e = blockIdx.z;
    const int cnt = g_cnt[e];
    const int mbase = blockIdx.x * 128;
    if (mbase >= cnt) return;
    const int nbase = blockIdx.y * 128;

    extern __shared__ __align__(16) char sm1[];
    int* rows = (int*)(sm1 + L1_ROWS);
    float* bias = (float*)(sm1 + L1_BIAS);
    const uint32_t sb = smem_u32(sm1);
    const uint32_t aA = sb + L1_A, aB = sb + L1_B;

    const int t = threadIdx.x;
    if (t < 128) {
        int p = mbase + t;
        rows[t] = (p < cnt) ? g_idx[e * BATCH + p] : -1;
        bias[t] = b1[e * FDIM2 + nbase + t];
    }
    __syncthreads();

    // ---- load mappings
    const int lr = t >> 1;             // row 0..127 (A and B share mapping)
    const int lo16 = (t & 1) * 16;     // 16-half offset within 32-half chunk row
    const int xr = rows[lr];
    const __half* xp = (xr >= 0) ? g_X16 + (size_t)xr * FDIM1 + lo16 : nullptr;
    const __half* wp = g_W1t + (size_t)(e * FDIM2 + nbase + lr) * FDIM1 + lo16;
    const uint32_t bOff = lr * (APITCH * 2) + (t & 1) * 32;

    uint4 xa[2];

#define L1_LOADA(kc)                                                       \
    do {                                                                   \
        if (xp) {                                                          \
            xa[0] = *(const uint4*)(xp + (kc));                            \
            xa[1] = *(const uint4*)(xp + (kc) + 8);                        \
        } else {                                                           \
            xa[0] = xa[1] = make_uint4(0, 0, 0, 0);                        \
        }                                                                  \
    } while (0)

#define L1_ISSUEB(kc, stg)                                                 \
    do {                                                                   \
        uint32_t so = (stg) * L1_STG + bOff;                               \
        cpasync16(aB + so,      wp + (kc));                                \
        cpasync16(aB + so + 16, wp + (kc) + 8);                            \
        CP_COMMIT();                                                       \
    } while (0)

    const int l = t & 31, wid = t >> 5;
    const int wm = (wid >> 2) * 64, wn = (wid & 3) * 32;
    const int lrow = l & 15;
    const int lk = (l >> 4) * 8;

    float acc[4][4][4];
#pragma unroll
    for (int i = 0; i < 4; i++)
#pragma unroll
        for (int j = 0; j < 4; j++)
#pragma unroll
            for (int q = 0; q < 4; q++) acc[i][j][q] = 0.f;

    // prologue: B chunk 0 in flight, A chunk 0 in regs
    L1_ISSUEB(0, 0);
    L1_LOADA(0);

    for (int c = 0; c < 32; c++) {
        const int stg = c & 1;
        __syncthreads();  // compute(c-1) fully done: safe to overwrite stage (c&1)

        // store A regs (chunk c) into sA[stg]
        {
            uint32_t d = aA + stg * L1_STG + lr * (APITCH * 2) + lo16 * 2;
            *(uint4*)(uintptr_t)(__cvta_shared_to_generic(d)) = xa[0];
            *(uint4*)(uintptr_t)(__cvta_shared_to_generic(d + 16)) = xa[1];
        }

        if (c + 1 < 32) {
            L1_ISSUEB((c + 1) * 32, stg ^ 1);  // next B into other stage
            L1_LOADA((c + 1) * 32);            // next A into regs
            CP_WAIT(1);                        // B(c) landed; B(c+1) in flight
        } else {
            CP_WAIT(0);
        }
        __syncthreads();

        // ---- compute chunk c from stage stg
        const uint32_t sOff = stg * L1_STG;
#pragma unroll
        for (int ks = 0; ks < 32; ks += 16) {
            uint32_t ah[4][4], bh[4][2];
#pragma unroll
            for (int mt = 0; mt < 4; mt++) {
                uint32_t off = sOff + ((wm + mt * 16 + lrow) * APITCH + ks + lk) * 2;
                ldsm4(ah[mt][0], ah[mt][1], ah[mt][2], ah[mt][3], aA + off);
            }
#pragma unroll
            for (int bg = 0; bg < 2; bg++) {
                uint32_t off = sOff + ((wn + bg * 16 + lrow) * APITCH + ks + lk) * 2;
                uint32_t r0, r1, r2, r3;
                ldsm4(r0, r1, r2, r3, aB + off);
                bh[2 * bg][0] = r0; bh[2 * bg + 1][0] = r1;
                bh[2 * bg][1] = r2; bh[2 * bg + 1][1] = r3;
            }
#pragma unroll
            for (int mt = 0; mt < 4; mt++)
#pragma unroll
                for (int nt = 0; nt < 4; nt++)
                    mma_fp16(acc[mt][nt], ah[mt], bh[nt][0], bh[nt][1]);
        }
    }

    // epilogue: + bias, relu, fp16, scatter to g_H
#pragma unroll
    for (int mt = 0; mt < 4; mt++) {
        int r0i = wm + mt * 16 + (l >> 2);
        int ra = rows[r0i], rb = rows[r0i + 8];
#pragma unroll
        for (int nt = 0; nt < 4; nt++) {
            int cl = wn + nt * 8 + (l & 3) * 2;
            float b0 = bias[cl], b1v = bias[cl + 1];
            if (ra >= 0) {
                uint32_t h = packh2(fmaxf(acc[mt][nt][0] + b0, 0.f),
                                    fmaxf(acc[mt][nt][1] + b1v, 0.f));
                *(uint32_t*)(&g_H[(size_t)ra * FDIM2 + nbase + cl]) = h;
            }
            if (rb >= 0) {
                uint32_t h = packh2(fmaxf(acc[mt][nt][2] + b0, 0.f),
                                    fmaxf(acc[mt][nt][3] + b1v, 0.f));
                *(uint32_t*)(&g_H[(size_t)rb * FDIM2 + nbase + cl]) = h;
            }
        }
    }
#undef L1_LOADA
#undef L1_ISSUEB
}

// ---------------- layer 2: fp16 mma.sync GEMM + softmax ---------------------
// CTA: 128 rows x 64 cols, K=512 in 16 chunks of 32. 8 warps = 4(M) x 2(N).
#define SM2_A 0
#define SM2_B 10240
#define SM2_SZ 34816  /* union with logits: 128 x 68 floats */

__global__ __launch_bounds__(256) void k_gemm2(
    const float* __restrict__ b2, float* __restrict__ out)
{
    const int e = blockIdx.y;
    const int cnt = g_cnt[e];
    const int mbase = blockIdx.x * 128;
    if (mbase >= cnt) return;

    __shared__ int rows[128];
    __shared__ float b2s[64];
    __shared__ __align__(16) char sm[SM2_SZ];

    const int t = threadIdx.x;
    if (t < 128) {
        int p = mbase + t;
        rows[t] = (p < cnt) ? g_idx[e * BATCH + p] : -1;
    }
    if (t < 64) b2s[t] = b2[e * NCLS + t];
    __syncthreads();

    __half* sA = (__half*)(sm + SM2_A);
    __half* sB = (__half*)(sm + SM2_B);

    const int lr = t >> 1;
    const int lo16 = (t & 1) * 16;
    const int hr = rows[lr];
    const __half* hp = (hr >= 0) ? g_H + (size_t)hr * FDIM2 + lo16 : nullptr;
    const int br = t >> 2, blo8 = (t & 3) * 8;
    const __half* wp = g_W2t + (size_t)(e * NCLS + br) * FDIM2 + blo8;

    uint4 ha[2], wb;

#define L2_LOAD(kc)                                                       \
    do {                                                                  \
        if (hp) {                                                         \
            ha[0] = *(const uint4*)(hp + (kc));                           \
            ha[1] = *(const uint4*)(hp + (kc) + 8);                       \
        } else {                                                          \
            ha[0] = ha[1] = make_uint4(0, 0, 0, 0);                       \
        }                                                                 \
        wb = *(const uint4*)(wp + (kc));                                  \
    } while (0)

    const int l = t & 31, wid = t >> 5;
    const int wm = (wid >> 1) * 32, wn = (wid & 1) * 32;
    const uint32_t aA = smem_u32(sA);
    const uint32_t aB = smem_u32(sB);
    const int lrow = l & 15;
    const int lk = (l >> 4) * 8;

    float acc[2][4][4];
#pragma unroll
    for (int i = 0; i < 2; i++)
#pragma unroll
        for (int j = 0; j < 4; j++)
#pragma unroll
            for (int q = 0; q < 4; q++) acc[i][j][q] = 0.f;

    L2_LOAD(0);

    for (int c = 0; c < 16; c++) {
        __syncthreads();
        *(uint4*)(&sA[lr * APITCH + lo16])      = ha[0];
        *(uint4*)(&sA[lr * APITCH + lo16 + 8])  = ha[1];
        *(uint4*)(&sB[br * APITCH + blo8])      = wb;
        __syncthreads();
        if (c < 15) L2_LOAD((c + 1) * 32);

#pragma unroll
        for (int ks = 0; ks < 32; ks += 16) {
            uint32_t ah[2][4], bh[4][2];
#pragma unroll
            for (int mt = 0; mt < 2; mt++) {
                uint32_t off = ((wm + mt * 16 + lrow) * APITCH + ks + lk) * 2;
                ldsm4(ah[mt][0], ah[mt][1], ah[mt][2], ah[mt][3], aA + off);
            }
#pragma unroll
            for (int bg = 0; bg < 2; bg++) {
                uint32_t off = ((wn + bg * 16 + lrow) * APITCH + ks + lk) * 2;
                uint32_t r0, r1, r2, r3;
                ldsm4(r0, r1, r2, r3, aB + off);
                bh[2 * bg][0] = r0; bh[2 * bg + 1][0] = r1;
                bh[2 * bg][1] = r2; bh[2 * bg + 1][1] = r3;
            }
#pragma unroll
            for (int mt = 0; mt < 2; mt++)
#pragma unroll
                for (int nt = 0; nt < 4; nt++)
                    mma_fp16(acc[mt][nt], ah[mt], bh[nt][0], bh[nt][1]);
        }
    }

    // logits -> smem (union over A/B buffers), then per-thread softmax
    __syncthreads();
    float* lg = (float*)sm;  // [128][68]
#pragma unroll
    for (int mt = 0; mt < 2; mt++) {
        int r0i = wm + mt * 16 + (l >> 2);
#pragma unroll
        for (int nt = 0; nt < 4; nt++) {
            int cl = wn + nt * 8 + (l & 3) * 2;
            lg[r0i * 68 + cl]           = acc[mt][nt][0];
            lg[r0i * 68 + cl + 1]       = acc[mt][nt][1];
            lg[(r0i + 8) * 68 + cl]     = acc[mt][nt][2];
            lg[(r0i + 8) * 68 + cl + 1] = acc[mt][nt][3];
        }
    }
    __syncthreads();

    if (t < 128) {
        int r = rows[t];
        if (r >= 0) {
            float v[64];
            float mx = -3.4e38f;
#pragma unroll
            for (int j = 0; j < 64; j++) {
                v[j] = lg[t * 68 + j] + b2s[j];
                mx = fmaxf(mx, v[j]);
            }
            float s = 0.f;
#pragma unroll
            for (int j = 0; j < 64; j++) {
                v[j] = __expf(v[j] - mx);
                s += v[j];
            }
            float inv = 1.0f / s;
            float4* op = (float4*)(out + (size_t)r * NCLS);
#pragma unroll
            for (int q = 0; q < 16; q++)
                op[q] = make_float4(v[4 * q] * inv, v[4 * q + 1] * inv,
                                    v[4 * q + 2] * inv, v[4 * q + 3] * inv);
        }
    }
#undef L2_LOAD
}

// ---------------------------------------------------------------------------
extern "C" void kernel_launch(void* const* d_in, const int* in_sizes, int n_in,
                              void* d_out, int out_size)
{
    const int*   domain = (const int*)  d_in[0];
    const float* x      = (const float*)d_in[1];
    const float* W1     = (const float*)d_in[2];
    const float* b1     = (const float*)d_in[3];
    const float* W2     = (const float*)d_in[4];
    const float* b2     = (const float*)d_in[5];
    float* out = (float*)d_out;

    cudaFuncSetAttribute(k_gemm1, cudaFuncAttributeMaxDynamicSharedMemorySize, L1_SMEM);

    k_reset<<<1, 32>>>();
    k_bucket<<<BATCH / 256, 256>>>(domain);
    k_convX<<<(BATCH * FDIM1 / 8) / 256, 256>>>(x);
    k_convW1<<<dim3(FDIM1 / 32, FDIM2 / 32, N_EXPERTS), dim3(32, 8)>>>(W1);
    k_convW2<<<dim3(FDIM2 / 32, NCLS / 32, N_EXPERTS), dim3(32, 8)>>>(W2);
    k_gemm1<<<dim3(BATCH / 128, FDIM2 / 128, N_EXPERTS), 256, L1_SMEM>>>(b1);
    k_gemm2<<<dim3(BATCH / 128, N_EXPERTS), 256>>>(b2, out);
}

// round 9
// speedup vs baseline: 1.4444x; 1.0341x over previous
#include <cuda_runtime.h>
#include <cuda_fp16.h>
#include <cstdint>

#define N_EXPERTS 8
#define FDIM1 1024
#define FDIM2 512
#define NCLS 64
#define BATCH 16384
#define APITCH 40    // gemm2 smem pitch (32 + 8 pad)
#define APITCH1 72   // gemm1 smem pitch for K-chunk 64 (64 + 8 pad)

// ---------------- scratch (static device arrays; allocation-free) ----------
__device__ __align__(16) __half g_W1t[N_EXPERTS * FDIM2 * FDIM1];
__device__ __align__(16) __half g_W2t[N_EXPERTS * NCLS * FDIM2];
__device__ __align__(16) __half g_X16[(size_t)BATCH * FDIM1];
__device__ __align__(16) __half g_H[(size_t)BATCH * FDIM2];
__device__ int g_idx[N_EXPERTS * BATCH];
__device__ int g_cnt[N_EXPERTS];

// ---------------- helpers ---------------------------------------------------
__device__ __forceinline__ uint32_t smem_u32(const void* p) {
    uint32_t a;
    asm("{ .reg .u64 t; cvta.to.shared.u64 t, %1; cvt.u32.u64 %0, t; }"
        : "=r"(a) : "l"(p));
    return a;
}

__device__ __forceinline__ void ldsm4(uint32_t& r0, uint32_t& r1, uint32_t& r2,
                                      uint32_t& r3, uint32_t addr) {
    asm volatile("ldmatrix.sync.aligned.m8n8.x4.shared.b16 {%0,%1,%2,%3}, [%4];"
                 : "=r"(r0), "=r"(r1), "=r"(r2), "=r"(r3) : "r"(addr));
}

__device__ __forceinline__ void mma_fp16(float* c, const uint32_t* a,
                                         uint32_t b0, uint32_t b1) {
    asm volatile(
        "mma.sync.aligned.m16n8k16.row.col.f32.f16.f16.f32 "
        "{%0,%1,%2,%3}, {%4,%5,%6,%7}, {%8,%9}, {%0,%1,%2,%3};"
        : "+f"(c[0]), "+f"(c[1]), "+f"(c[2]), "+f"(c[3])
        : "r"(a[0]), "r"(a[1]), "r"(a[2]), "r"(a[3]), "r"(b0), "r"(b1));
}

__device__ __forceinline__ void cpasync16(uint32_t dst, const void* src) {
    asm volatile("cp.async.ca.shared.global [%0], [%1], 16;"
                 :: "r"(dst), "l"(src) : "memory");
}
#define CP_COMMIT() asm volatile("cp.async.commit_group;" ::: "memory")
#define CP_WAIT(n) asm volatile("cp.async.wait_group %0;" ::"n"(n) : "memory")

__device__ __forceinline__ uint32_t packh2(float v0, float v1) {
    __half2 h = __floats2half2_rn(v0, v1);
    return *(uint32_t*)&h;
}

// ---------------- small kernels ---------------------------------------------
__global__ void k_reset() {
    if (threadIdx.x < N_EXPERTS) g_cnt[threadIdx.x] = 0;
}

__global__ void k_bucket(const int* __restrict__ domain) {
    int i = blockIdx.x * blockDim.x + threadIdx.x;
    if (i < BATCH) {
        int e = domain[i];
        int p = atomicAdd(&g_cnt[e], 1);
        g_idx[e * BATCH + p] = i;
    }
}

// Convert x fp32 -> fp16 (no transpose)
__global__ void k_convX(const float* __restrict__ src) {
    size_t i = ((size_t)blockIdx.x * blockDim.x + threadIdx.x) * 8;
    float4 a = *(const float4*)(src + i);
    float4 b = *(const float4*)(src + i + 4);
    uint4 o = make_uint4(packh2(a.x, a.y), packh2(a.z, a.w),
                         packh2(b.x, b.y), packh2(b.z, b.w));
    *(uint4*)(&g_X16[i]) = o;
}

// Transpose+convert W1 [e][k=1024][n=512] fp32 -> [e][n][k] fp16
__global__ void k_convW1(const float* __restrict__ src) {
    __shared__ float tile[32][33];
    int e = blockIdx.z;
    int kb = blockIdx.x * 32, nb = blockIdx.y * 32;
    const float* s = src + ((size_t)e * FDIM1 + kb) * FDIM2 + nb;
    int tx = threadIdx.x, ty = threadIdx.y;
#pragma unroll
    for (int i = 0; i < 32; i += 8) tile[ty + i][tx] = s[(size_t)(ty + i) * FDIM2 + tx];
    __syncthreads();
    size_t ob = ((size_t)e * FDIM2 + nb) * FDIM1 + kb;
#pragma unroll
    for (int i = 0; i < 32; i += 8)
        g_W1t[ob + (size_t)(ty + i) * FDIM1 + tx] = __float2half_rn(tile[tx][ty + i]);
}

// Transpose+convert W2 [e][k=512][n=64] fp32 -> [e][n][k] fp16
__global__ void k_convW2(const float* __restrict__ src) {
    __shared__ float tile[32][33];
    int e = blockIdx.z;
    int kb = blockIdx.x * 32, nb = blockIdx.y * 32;
    const float* s = src + ((size_t)e * FDIM2 + kb) * NCLS + nb;
    int tx = threadIdx.x, ty = threadIdx.y;
#pragma unroll
    for (int i = 0; i < 32; i += 8) tile[ty + i][tx] = s[(size_t)(ty + i) * NCLS + tx];
    __syncthreads();
    size_t ob = ((size_t)e * NCLS + nb) * FDIM2 + kb;
#pragma unroll
    for (int i = 0; i < 32; i += 8)
        g_W2t[ob + (size_t)(ty + i) * FDIM2 + tx] = __float2half_rn(tile[tx][ty + i]);
}

// ---------------- layer 1: fp16 mma.sync GEMM, K-chunk 64 -------------------
// CTA: 128 rows x 128 cols, K=1024 in 16 chunks of 64. 8 warps = 2(M) x 4(N).
// 2-stage double buffer; B via cp.async + wait(1), A via LDG regs -> STS.
// Dynamic smem (bytes):
//   [0,512)    int rows[128]
//   [512,1024) float bias[128]
//   [1024,...) 2 stages x { A 18432 | B 18432 }
#define L1_ROWS 0
#define L1_BIAS 512
#define L1_BASE 1024
#define L1_ASTG 18432
#define L1_STG 36864
#define L1_SMEM (1024 + 2 * L1_STG)

__global__ __launch_bounds__(256, 2) void k_gemm1(const float* __restrict__ b1)
{
    const int e = blockIdx.z;
    const int cnt = g_cnt[e];
    const int mbase = blockIdx.x * 128;
    if (mbase >= cnt) return;
    const int nbase = blockIdx.y * 128;

    extern __shared__ __align__(16) char sm1[];
    int* rows = (int*)(sm1 + L1_ROWS);
    float* bias = (float*)(sm1 + L1_BIAS);
    const uint32_t sb = smem_u32(sm1);

    const int t = threadIdx.x;
    if (t < 128) {
        int p = mbase + t;
        rows[t] = (p < cnt) ? g_idx[e * BATCH + p] : -1;
        bias[t] = b1[e * FDIM2 + nbase + t];
    }
    __syncthreads();

    // ---- load mappings: thread -> (row lr, 32-half segment seg)
    const int lr = t >> 1;
    const int seg = t & 1;
    const int xr = rows[lr];
    const __half* xp = (xr >= 0) ? g_X16 + (size_t)xr * FDIM1 + seg * 32 : nullptr;
    const __half* wp = g_W1t + (size_t)(e * FDIM2 + nbase + lr) * FDIM1 + seg * 32;
    const uint32_t tOff = lr * (APITCH1 * 2) + seg * 64;  // byte offset in stage

    uint4 xa[4];

#define L1_LOADA(kc)                                                       \
    do {                                                                   \
        if (xp) {                                                          \
            xa[0] = *(const uint4*)(xp + (kc));                            \
            xa[1] = *(const uint4*)(xp + (kc) + 8);                        \
            xa[2] = *(const uint4*)(xp + (kc) + 16);                       \
            xa[3] = *(const uint4*)(xp + (kc) + 24);                       \
        } else {                                                           \
            xa[0] = xa[1] = xa[2] = xa[3] = make_uint4(0, 0, 0, 0);        \
        }                                                                  \
    } while (0)

#define L1_ISSUEB(kc, stg)                                                 \
    do {                                                                   \
        uint32_t so = sb + L1_BASE + (stg) * L1_STG + L1_ASTG + tOff;      \
        cpasync16(so,      wp + (kc));                                     \
        cpasync16(so + 16, wp + (kc) + 8);                                 \
        cpasync16(so + 32, wp + (kc) + 16);                                \
        cpasync16(so + 48, wp + (kc) + 24);                                \
        CP_COMMIT();                                                       \
    } while (0)

    const int l = t & 31, wid = t >> 5;
    const int wm = (wid >> 2) * 64, wn = (wid & 3) * 32;
    const int lrow = l & 15;
    const int lk = (l >> 4) * 8;

    float acc[4][4][4];
#pragma unroll
    for (int i = 0; i < 4; i++)
#pragma unroll
        for (int j = 0; j < 4; j++)
#pragma unroll
            for (int q = 0; q < 4; q++) acc[i][j][q] = 0.f;

    // prologue: B chunk 0 in flight, A chunk 0 in regs
    L1_ISSUEB(0, 0);
    L1_LOADA(0);

    for (int c = 0; c < 16; c++) {
        const int stg = c & 1;
        __syncthreads();  // compute(c-1) done: stage stg reusable

        // store A regs (chunk c) into sA[stg]
        {
            uint32_t d = sb + L1_BASE + stg * L1_STG + tOff;
            *(uint4*)(uintptr_t)(__cvta_shared_to_generic(d))      = xa[0];
            *(uint4*)(uintptr_t)(__cvta_shared_to_generic(d + 16)) = xa[1];
            *(uint4*)(uintptr_t)(__cvta_shared_to_generic(d + 32)) = xa[2];
            *(uint4*)(uintptr_t)(__cvta_shared_to_generic(d + 48)) = xa[3];
        }

        if (c + 1 < 16) {
            L1_ISSUEB((c + 1) * 64, stg ^ 1);  // next B into other stage
            L1_LOADA((c + 1) * 64);            // next A into regs
            CP_WAIT(1);                        // B(c) landed; B(c+1) in flight
        } else {
            CP_WAIT(0);
        }
        __syncthreads();

        // ---- compute chunk c from stage stg
        const uint32_t aA = sb + L1_BASE + stg * L1_STG;
        const uint32_t aB = aA + L1_ASTG;
#pragma unroll
        for (int ks = 0; ks < 64; ks += 16) {
            uint32_t ah[4][4], bh[4][2];
#pragma unroll
            for (int mt = 0; mt < 4; mt++) {
                uint32_t off = ((wm + mt * 16 + lrow) * APITCH1 + ks + lk) * 2;
                ldsm4(ah[mt][0], ah[mt][1], ah[mt][2], ah[mt][3], aA + off);
            }
#pragma unroll
            for (int bg = 0; bg < 2; bg++) {
                uint32_t off = ((wn + bg * 16 + lrow) * APITCH1 + ks + lk) * 2;
                uint32_t r0, r1, r2, r3;
                ldsm4(r0, r1, r2, r3, aB + off);
                bh[2 * bg][0] = r0; bh[2 * bg + 1][0] = r1;
                bh[2 * bg][1] = r2; bh[2 * bg + 1][1] = r3;
            }
#pragma unroll
            for (int mt = 0; mt < 4; mt++)
#pragma unroll
                for (int nt = 0; nt < 4; nt++)
                    mma_fp16(acc[mt][nt], ah[mt], bh[nt][0], bh[nt][1]);
        }
    }

    // epilogue: + bias, relu, fp16, scatter to g_H
#pragma unroll
    for (int mt = 0; mt < 4; mt++) {
        int r0i = wm + mt * 16 + (l >> 2);
        int ra = rows[r0i], rb = rows[r0i + 8];
#pragma unroll
        for (int nt = 0; nt < 4; nt++) {
            int cl = wn + nt * 8 + (l & 3) * 2;
            float b0 = bias[cl], b1v = bias[cl + 1];
            if (ra >= 0) {
                uint32_t h = packh2(fmaxf(acc[mt][nt][0] + b0, 0.f),
                                    fmaxf(acc[mt][nt][1] + b1v, 0.f));
                *(uint32_t*)(&g_H[(size_t)ra * FDIM2 + nbase + cl]) = h;
            }
            if (rb >= 0) {
                uint32_t h = packh2(fmaxf(acc[mt][nt][2] + b0, 0.f),
                                    fmaxf(acc[mt][nt][3] + b1v, 0.f));
                *(uint32_t*)(&g_H[(size_t)rb * FDIM2 + nbase + cl]) = h;
            }
        }
    }
#undef L1_LOADA
#undef L1_ISSUEB
}

// ---------------- layer 2: fp16 mma.sync GEMM + softmax ---------------------
// CTA: 128 rows x 64 cols, K=512 in 16 chunks of 32. 8 warps = 4(M) x 2(N).
#define SM2_A 0
#define SM2_B 10240
#define SM2_SZ 34816  /* union with logits: 128 x 68 floats */

__global__ __launch_bounds__(256) void k_gemm2(
    const float* __restrict__ b2, float* __restrict__ out)
{
    const int e = blockIdx.y;
    const int cnt = g_cnt[e];
    const int mbase = blockIdx.x * 128;
    if (mbase >= cnt) return;

    __shared__ int rows[128];
    __shared__ float b2s[64];
    __shared__ __align__(16) char sm[SM2_SZ];

    const int t = threadIdx.x;
    if (t < 128) {
        int p = mbase + t;
        rows[t] = (p < cnt) ? g_idx[e * BATCH + p] : -1;
    }
    if (t < 64) b2s[t] = b2[e * NCLS + t];
    __syncthreads();

    __half* sA = (__half*)(sm + SM2_A);
    __half* sB = (__half*)(sm + SM2_B);

    const int lr = t >> 1;
    const int lo16 = (t & 1) * 16;
    const int hr = rows[lr];
    const __half* hp = (hr >= 0) ? g_H + (size_t)hr * FDIM2 + lo16 : nullptr;
    const int br = t >> 2, blo8 = (t & 3) * 8;
    const __half* wp = g_W2t + (size_t)(e * NCLS + br) * FDIM2 + blo8;

    uint4 ha[2], wb;

#define L2_LOAD(kc)                                                       \
    do {                                                                  \
        if (hp) {                                                         \
            ha[0] = *(const uint4*)(hp + (kc));                           \
            ha[1] = *(const uint4*)(hp + (kc) + 8);                       \
        } else {                                                          \
            ha[0] = ha[1] = make_uint4(0, 0, 0, 0);                       \
        }                                                                 \
        wb = *(const uint4*)(wp + (kc));                                  \
    } while (0)

    const int l = t & 31, wid = t >> 5;
    const int wm = (wid >> 1) * 32, wn = (wid & 1) * 32;
    const uint32_t aA = smem_u32(sA);
    const uint32_t aB = smem_u32(sB);
    const int lrow = l & 15;
    const int lk = (l >> 4) * 8;

    float acc[2][4][4];
#pragma unroll
    for (int i = 0; i < 2; i++)
#pragma unroll
        for (int j = 0; j < 4; j++)
#pragma unroll
            for (int q = 0; q < 4; q++) acc[i][j][q] = 0.f;

    L2_LOAD(0);

    for (int c = 0; c < 16; c++) {
        __syncthreads();
        *(uint4*)(&sA[lr * APITCH + lo16])      = ha[0];
        *(uint4*)(&sA[lr * APITCH + lo16 + 8])  = ha[1];
        *(uint4*)(&sB[br * APITCH + blo8])      = wb;
        __syncthreads();
        if (c < 15) L2_LOAD((c + 1) * 32);

#pragma unroll
        for (int ks = 0; ks < 32; ks += 16) {
            uint32_t ah[2][4], bh[4][2];
#pragma unroll
            for (int mt = 0; mt < 2; mt++) {
                uint32_t off = ((wm + mt * 16 + lrow) * APITCH + ks + lk) * 2;
                ldsm4(ah[mt][0], ah[mt][1], ah[mt][2], ah[mt][3], aA + off);
            }
#pragma unroll
            for (int bg = 0; bg < 2; bg++) {
                uint32_t off = ((wn + bg * 16 + lrow) * APITCH + ks + lk) * 2;
                uint32_t r0, r1, r2, r3;
                ldsm4(r0, r1, r2, r3, aB + off);
                bh[2 * bg][0] = r0; bh[2 * bg + 1][0] = r1;
                bh[2 * bg][1] = r2; bh[2 * bg + 1][1] = r3;
            }
#pragma unroll
            for (int mt = 0; mt < 2; mt++)
#pragma unroll
                for (int nt = 0; nt < 4; nt++)
                    mma_fp16(acc[mt][nt], ah[mt], bh[nt][0], bh[nt][1]);
        }
    }

    // logits -> smem (union over A/B buffers), then per-thread softmax
    __syncthreads();
    float* lg = (float*)sm;  // [128][68]
#pragma unroll
    for (int mt = 0; mt < 2; mt++) {
        int r0i = wm + mt * 16 + (l >> 2);
#pragma unroll
        for (int nt = 0; nt < 4; nt++) {
            int cl = wn + nt * 8 + (l & 3) * 2;
            lg[r0i * 68 + cl]           = acc[mt][nt][0];
            lg[r0i * 68 + cl + 1]       = acc[mt][nt][1];
            lg[(r0i + 8) * 68 + cl]     = acc[mt][nt][2];
            lg[(r0i + 8) * 68 + cl + 1] = acc[mt][nt][3];
        }
    }
    __syncthreads();

    if (t < 128) {
        int r = rows[t];
        if (r >= 0) {
            float v[64];
            float mx = -3.4e38f;
#pragma unroll
            for (int j = 0; j < 64; j++) {
                v[j] = lg[t * 68 + j] + b2s[j];
                mx = fmaxf(mx, v[j]);
            }
            float s = 0.f;
#pragma unroll
            for (int j = 0; j < 64; j++) {
                v[j] = __expf(v[j] - mx);
                s += v[j];
            }
            float inv = 1.0f / s;
            float4* op = (float4*)(out + (size_t)r * NCLS);
#pragma unroll
            for (int q = 0; q < 16; q++)
                op[q] = make_float4(v[4 * q] * inv, v[4 * q + 1] * inv,
                                    v[4 * q + 2] * inv, v[4 * q + 3] * inv);
        }
    }
#undef L2_LOAD
}

// ---------------------------------------------------------------------------
extern "C" void kernel_launch(void* const* d_in, const int* in_sizes, int n_in,
                              void* d_out, int out_size)
{
    const int*   domain = (const int*)  d_in[0];
    const float* x      = (const float*)d_in[1];
    const float* W1     = (const float*)d_in[2];
    const float* b1     = (const float*)d_in[3];
    const float* W2     = (const float*)d_in[4];
    const float* b2     = (const float*)d_in[5];
    float* out = (float*)d_out;

    cudaFuncSetAttribute(k_gemm1, cudaFuncAttributeMaxDynamicSharedMemorySize, L1_SMEM);

    k_reset<<<1, 32>>>();
    k_bucket<<<BATCH / 256, 256>>>(domain);
    k_convX<<<(BATCH * FDIM1 / 8) / 256, 256>>>(x);
    k_convW1<<<dim3(FDIM1 / 32, FDIM2 / 32, N_EXPERTS), dim3(32, 8)>>>(W1);
    k_convW2<<<dim3(FDIM2 / 32, NCLS / 32, N_EXPERTS), dim3(32, 8)>>>(W2);
    k_gemm1<<<dim3(BATCH / 128, FDIM2 / 128, N_EXPERTS), 256, L1_SMEM>>>(b1);
    k_gemm2<<<dim3(BATCH / 128, N_EXPERTS), 256>>>(b2, out);
}

// round 10
// speedup vs baseline: 1.4895x; 1.0313x over previous
#include <cuda_runtime.h>
#include <cuda_fp16.h>
#include <cstdint>

#define N_EXPERTS 8
#define FDIM1 1024
#define FDIM2 512
#define NCLS 64
#define BATCH 16384
#define APITCH1 72   // smem pitch for K-chunk 64 (64 + 8 pad), conflict-free ldmatrix

// ---------------- scratch (static device arrays; allocation-free) ----------
__device__ __align__(16) __half g_W1t[N_EXPERTS * FDIM2 * FDIM1];
__device__ __align__(16) __half g_W2t[N_EXPERTS * NCLS * FDIM2];
__device__ __align__(16) __half g_X16[(size_t)BATCH * FDIM1];
__device__ __align__(16) __half g_H[(size_t)BATCH * FDIM2];
__device__ int g_idx[N_EXPERTS * BATCH];
__device__ int g_cnt[N_EXPERTS];   // zero-init at load; reset each launch in k_convX

// ---------------- helpers ---------------------------------------------------
__device__ __forceinline__ uint32_t smem_u32(const void* p) {
    uint32_t a;
    asm("{ .reg .u64 t; cvta.to.shared.u64 t, %1; cvt.u32.u64 %0, t; }"
        : "=r"(a) : "l"(p));
    return a;
}

__device__ __forceinline__ void ldsm4(uint32_t& r0, uint32_t& r1, uint32_t& r2,
                                      uint32_t& r3, uint32_t addr) {
    asm volatile("ldmatrix.sync.aligned.m8n8.x4.shared.b16 {%0,%1,%2,%3}, [%4];"
                 : "=r"(r0), "=r"(r1), "=r"(r2), "=r"(r3) : "r"(addr));
}

__device__ __forceinline__ void mma_fp16(float* c, const uint32_t* a,
                                         uint32_t b0, uint32_t b1) {
    asm volatile(
        "mma.sync.aligned.m16n8k16.row.col.f32.f16.f16.f32 "
        "{%0,%1,%2,%3}, {%4,%5,%6,%7}, {%8,%9}, {%0,%1,%2,%3};"
        : "+f"(c[0]), "+f"(c[1]), "+f"(c[2]), "+f"(c[3])
        : "r"(a[0]), "r"(a[1]), "r"(a[2]), "r"(a[3]), "r"(b0), "r"(b1));
}

__device__ __forceinline__ void cpasync16(uint32_t dst, const void* src) {
    asm volatile("cp.async.ca.shared.global [%0], [%1], 16;"
                 :: "r"(dst), "l"(src) : "memory");
}
__device__ __forceinline__ void cpasync16z(uint32_t dst, const void* src, int sz) {
    asm volatile("cp.async.ca.shared.global [%0], [%1], 16, %2;"
                 :: "r"(dst), "l"(src), "r"(sz) : "memory");
}
#define CP_COMMIT() asm volatile("cp.async.commit_group;" ::: "memory")
#define CP_WAIT(n) asm volatile("cp.async.wait_group %0;" ::"n"(n) : "memory")

__device__ __forceinline__ uint32_t packh2(float v0, float v1) {
    __half2 h = __floats2half2_rn(v0, v1);
    return *(uint32_t*)&h;
}

// ---------------- prep kernels ----------------------------------------------
// convX also resets g_cnt (runs strictly before k_bucket)
__global__ void k_convX(const float* __restrict__ src) {
    if (blockIdx.x == 0 && threadIdx.x < N_EXPERTS) g_cnt[threadIdx.x] = 0;
    size_t i = ((size_t)blockIdx.x * blockDim.x + threadIdx.x) * 8;
    float4 a = *(const float4*)(src + i);
    float4 b = *(const float4*)(src + i + 4);
    uint4 o = make_uint4(packh2(a.x, a.y), packh2(a.z, a.w),
                         packh2(b.x, b.y), packh2(b.z, b.w));
    *(uint4*)(&g_X16[i]) = o;
}

__global__ void k_bucket(const int* __restrict__ domain) {
    int i = blockIdx.x * blockDim.x + threadIdx.x;
    if (i < BATCH) {
        int e = domain[i];
        int p = atomicAdd(&g_cnt[e], 1);
        g_idx[e * BATCH + p] = i;
    }
}

// Merged transpose+convert for W1 and W2.
// blockIdx.y < 16: W1 tile; blockIdx.y in [16,18): W2 tile (x < 16 only).
__global__ void k_convW(const float* __restrict__ W1,
                        const float* __restrict__ W2) {
    __shared__ float tile[32][33];
    int e = blockIdx.z;
    int tx = threadIdx.x, ty = threadIdx.y;
    if (blockIdx.y < 16) {
        int kb = blockIdx.x * 32, nb = blockIdx.y * 32;
        const float* s = W1 + ((size_t)e * FDIM1 + kb) * FDIM2 + nb;
#pragma unroll
        for (int i = 0; i < 32; i += 8) tile[ty + i][tx] = s[(size_t)(ty + i) * FDIM2 + tx];
        __syncthreads();
        size_t ob = ((size_t)e * FDIM2 + nb) * FDIM1 + kb;
#pragma unroll
        for (int i = 0; i < 32; i += 8)
            g_W1t[ob + (size_t)(ty + i) * FDIM1 + tx] = __float2half_rn(tile[tx][ty + i]);
    } else {
        if (blockIdx.x >= 16) return;
        int kb = blockIdx.x * 32, nb = (blockIdx.y - 16) * 32;
        const float* s = W2 + ((size_t)e * FDIM2 + kb) * NCLS + nb;
#pragma unroll
        for (int i = 0; i < 32; i += 8) tile[ty + i][tx] = s[(size_t)(ty + i) * NCLS + tx];
        __syncthreads();
        size_t ob = ((size_t)e * NCLS + nb) * FDIM2 + kb;
#pragma unroll
        for (int i = 0; i < 32; i += 8)
            g_W2t[ob + (size_t)(ty + i) * FDIM2 + tx] = __float2half_rn(tile[tx][ty + i]);
    }
}

// ---------------- layer 1: fp16 mma.sync GEMM, K-chunk 64 -------------------
// CTA: 128 rows x 128 cols, K=1024 in 16 chunks of 64. 8 warps = 2(M) x 4(N).
// 2-stage double buffer; B via cp.async + wait(1), A via LDG regs -> STS.
#define L1_ROWS 0
#define L1_BIAS 512
#define L1_BASE 1024
#define L1_ASTG 18432
#define L1_STG 36864
#define L1_SMEM (1024 + 2 * L1_STG)

__global__ __launch_bounds__(256, 2) void k_gemm1(const float* __restrict__ b1)
{
    const int e = blockIdx.z;
    const int cnt = g_cnt[e];
    const int mbase = blockIdx.x * 128;
    if (mbase >= cnt) return;
    const int nbase = blockIdx.y * 128;

    extern __shared__ __align__(16) char sm1[];
    int* rows = (int*)(sm1 + L1_ROWS);
    float* bias = (float*)(sm1 + L1_BIAS);
    const uint32_t sb = smem_u32(sm1);

    const int t = threadIdx.x;
    if (t < 128) {
        int p = mbase + t;
        rows[t] = (p < cnt) ? g_idx[e * BATCH + p] : -1;
        bias[t] = b1[e * FDIM2 + nbase + t];
    }
    __syncthreads();

    const int lr = t >> 1;
    const int seg = t & 1;
    const int xr = rows[lr];
    const __half* xp = (xr >= 0) ? g_X16 + (size_t)xr * FDIM1 + seg * 32 : nullptr;
    const __half* wp = g_W1t + (size_t)(e * FDIM2 + nbase + lr) * FDIM1 + seg * 32;
    const uint32_t tOff = lr * (APITCH1 * 2) + seg * 64;

    uint4 xa[4];

#define L1_LOADA(kc)                                                       \
    do {                                                                   \
        if (xp) {                                                          \
            xa[0] = *(const uint4*)(xp + (kc));                            \
            xa[1] = *(const uint4*)(xp + (kc) + 8);                        \
            xa[2] = *(const uint4*)(xp + (kc) + 16);                       \
            xa[3] = *(const uint4*)(xp + (kc) + 24);                       \
        } else {                                                           \
            xa[0] = xa[1] = xa[2] = xa[3] = make_uint4(0, 0, 0, 0);        \
        }                                                                  \
    } while (0)

#define L1_ISSUEB(kc, stg)                                                 \
    do {                                                                   \
        uint32_t so = sb + L1_BASE + (stg) * L1_STG + L1_ASTG + tOff;      \
        cpasync16(so,      wp + (kc));                                     \
        cpasync16(so + 16, wp + (kc) + 8);                                 \
        cpasync16(so + 32, wp + (kc) + 16);                                \
        cpasync16(so + 48, wp + (kc) + 24);                                \
        CP_COMMIT();                                                       \
    } while (0)

    const int l = t & 31, wid = t >> 5;
    const int wm = (wid >> 2) * 64, wn = (wid & 3) * 32;
    const int lrow = l & 15;
    const int lk = (l >> 4) * 8;

    float acc[4][4][4];
#pragma unroll
    for (int i = 0; i < 4; i++)
#pragma unroll
        for (int j = 0; j < 4; j++)
#pragma unroll
            for (int q = 0; q < 4; q++) acc[i][j][q] = 0.f;

    L1_ISSUEB(0, 0);
    L1_LOADA(0);

    for (int c = 0; c < 16; c++) {
        const int stg = c & 1;
        __syncthreads();

        {
            uint32_t d = sb + L1_BASE + stg * L1_STG + tOff;
            *(uint4*)(uintptr_t)(__cvta_shared_to_generic(d))      = xa[0];
            *(uint4*)(uintptr_t)(__cvta_shared_to_generic(d + 16)) = xa[1];
            *(uint4*)(uintptr_t)(__cvta_shared_to_generic(d + 32)) = xa[2];
            *(uint4*)(uintptr_t)(__cvta_shared_to_generic(d + 48)) = xa[3];
        }

        if (c + 1 < 16) {
            L1_ISSUEB((c + 1) * 64, stg ^ 1);
            L1_LOADA((c + 1) * 64);
            CP_WAIT(1);
        } else {
            CP_WAIT(0);
        }
        __syncthreads();

        const uint32_t aA = sb + L1_BASE + stg * L1_STG;
        const uint32_t aB = aA + L1_ASTG;
#pragma unroll
        for (int ks = 0; ks < 64; ks += 16) {
            uint32_t ah[4][4], bh[4][2];
#pragma unroll
            for (int mt = 0; mt < 4; mt++) {
                uint32_t off = ((wm + mt * 16 + lrow) * APITCH1 + ks + lk) * 2;
                ldsm4(ah[mt][0], ah[mt][1], ah[mt][2], ah[mt][3], aA + off);
            }
#pragma unroll
            for (int bg = 0; bg < 2; bg++) {
                uint32_t off = ((wn + bg * 16 + lrow) * APITCH1 + ks + lk) * 2;
                uint32_t r0, r1, r2, r3;
                ldsm4(r0, r1, r2, r3, aB + off);
                bh[2 * bg][0] = r0; bh[2 * bg + 1][0] = r1;
                bh[2 * bg][1] = r2; bh[2 * bg + 1][1] = r3;
            }
#pragma unroll
            for (int mt = 0; mt < 4; mt++)
#pragma unroll
                for (int nt = 0; nt < 4; nt++)
                    mma_fp16(acc[mt][nt], ah[mt], bh[nt][0], bh[nt][1]);
        }
    }

    // epilogue: + bias, relu, fp16, scatter to g_H
#pragma unroll
    for (int mt = 0; mt < 4; mt++) {
        int r0i = wm + mt * 16 + (l >> 2);
        int ra = rows[r0i], rb = rows[r0i + 8];
#pragma unroll
        for (int nt = 0; nt < 4; nt++) {
            int cl = wn + nt * 8 + (l & 3) * 2;
            float b0 = bias[cl], b1v = bias[cl + 1];
            if (ra >= 0) {
                uint32_t h = packh2(fmaxf(acc[mt][nt][0] + b0, 0.f),
                                    fmaxf(acc[mt][nt][1] + b1v, 0.f));
                *(uint32_t*)(&g_H[(size_t)ra * FDIM2 + nbase + cl]) = h;
            }
            if (rb >= 0) {
                uint32_t h = packh2(fmaxf(acc[mt][nt][2] + b0, 0.f),
                                    fmaxf(acc[mt][nt][3] + b1v, 0.f));
                *(uint32_t*)(&g_H[(size_t)rb * FDIM2 + nbase + cl]) = h;
            }
        }
    }
#undef L1_LOADA
#undef L1_ISSUEB
}

// ---------------- layer 2: fp16 mma.sync, K-chunk 64, cp.async, softmax -----
// CTA: 128 rows x 64 cols, K=512 in 8 chunks of 64. 8 warps = 4(M) x 2(N).
// Dynamic smem:
//   [0,512)    int rows[128]
//   [512,768)  float b2s[64]
//   [1024,...) 2 stages x { A 18432 | B 9216 }  (27648/stage)
//   logits union at [1024, 1024+34816)
#define L2_ROWS 0
#define L2_B2S 512
#define L2_BASE 1024
#define L2_ASTG 18432
#define L2_STG 27648
#define L2_SMEM (1024 + 2 * L2_STG)

__global__ __launch_bounds__(256) void k_gemm2(
    const float* __restrict__ b2, float* __restrict__ out)
{
    const int e = blockIdx.y;
    const int cnt = g_cnt[e];
    const int mbase = blockIdx.x * 128;
    if (mbase >= cnt) return;

    extern __shared__ __align__(16) char sm2[];
    int* rows = (int*)(sm2 + L2_ROWS);
    float* b2s = (float*)(sm2 + L2_B2S);
    const uint32_t sb = smem_u32(sm2);

    const int t = threadIdx.x;
    if (t < 128) {
        int p = mbase + t;
        rows[t] = (p < cnt) ? g_idx[e * BATCH + p] : -1;
    }
    if (t < 64) b2s[t] = b2[e * NCLS + t];
    __syncthreads();

    // A mapping: row lr = t>>1, seg = t&1 (32 halfs = 64 B)
    const int lr = t >> 1;
    const int seg = t & 1;
    const int hr = rows[lr];
    const __half* hp = (hr >= 0) ? g_H + (size_t)hr * FDIM2 + seg * 32 : g_H;
    const int hsz = (hr >= 0) ? 16 : 0;
    const uint32_t aOff = lr * (APITCH1 * 2) + seg * 64;
    // B mapping: row br = t>>2 (0..63), 32B segment bs = t&3
    const int br = t >> 2, bs = t & 3;
    const __half* wp = g_W2t + (size_t)(e * NCLS + br) * FDIM2 + bs * 16;
    const uint32_t bOff = br * (APITCH1 * 2) + bs * 32;

#define L2_ISSUE(kc, stg)                                                  \
    do {                                                                   \
        uint32_t ba = sb + L2_BASE + (stg) * L2_STG;                       \
        cpasync16z(ba + aOff,      hp + (kc), hsz);                        \
        cpasync16z(ba + aOff + 16, hp + (kc) + 8, hsz);                    \
        cpasync16z(ba + aOff + 32, hp + (kc) + 16, hsz);                   \
        cpasync16z(ba + aOff + 48, hp + (kc) + 24, hsz);                   \
        cpasync16(ba + L2_ASTG + bOff,      wp + (kc));                    \
        cpasync16(ba + L2_ASTG + bOff + 16, wp + (kc) + 8);                \
        CP_COMMIT();                                                       \
    } while (0)

    const int l = t & 31, wid = t >> 5;
    const int wm = (wid >> 1) * 32, wn = (wid & 1) * 32;
    const int lrow = l & 15;
    const int lk = (l >> 4) * 8;

    float acc[2][4][4];
#pragma unroll
    for (int i = 0; i < 2; i++)
#pragma unroll
        for (int j = 0; j < 4; j++)
#pragma unroll
            for (int q = 0; q < 4; q++) acc[i][j][q] = 0.f;

    L2_ISSUE(0, 0);

    for (int c = 0; c < 8; c++) {
        const int stg = c & 1;
        __syncthreads();  // compute(c-1) done: stage stg^1 free for next issue
        if (c + 1 < 8) {
            L2_ISSUE((c + 1) * 64, stg ^ 1);
            CP_WAIT(1);
        } else {
            CP_WAIT(0);
        }
        __syncthreads();

        const uint32_t aA = sb + L2_BASE + stg * L2_STG;
        const uint32_t aB = aA + L2_ASTG;
#pragma unroll
        for (int ks = 0; ks < 64; ks += 16) {
            uint32_t ah[2][4], bh[4][2];
#pragma unroll
            for (int mt = 0; mt < 2; mt++) {
                uint32_t off = ((wm + mt * 16 + lrow) * APITCH1 + ks + lk) * 2;
                ldsm4(ah[mt][0], ah[mt][1], ah[mt][2], ah[mt][3], aA + off);
            }
#pragma unroll
            for (int bg = 0; bg < 2; bg++) {
                uint32_t off = ((wn + bg * 16 + lrow) * APITCH1 + ks + lk) * 2;
                uint32_t r0, r1, r2, r3;
                ldsm4(r0, r1, r2, r3, aB + off);
                bh[2 * bg][0] = r0; bh[2 * bg + 1][0] = r1;
                bh[2 * bg][1] = r2; bh[2 * bg + 1][1] = r3;
            }
#pragma unroll
            for (int mt = 0; mt < 2; mt++)
#pragma unroll
                for (int nt = 0; nt < 4; nt++)
                    mma_fp16(acc[mt][nt], ah[mt], bh[nt][0], bh[nt][1]);
        }
    }

    // logits -> smem (stage union at L2_BASE), then per-thread softmax
    __syncthreads();
    float* lg = (float*)(sm2 + L2_BASE);  // [128][68]
#pragma unroll
    for (int mt = 0; mt < 2; mt++) {
        int r0i = wm + mt * 16 + (l >> 2);
#pragma unroll
        for (int nt = 0; nt < 4; nt++) {
            int cl = wn + nt * 8 + (l & 3) * 2;
            lg[r0i * 68 + cl]           = acc[mt][nt][0];
            lg[r0i * 68 + cl + 1]       = acc[mt][nt][1];
            lg[(r0i + 8) * 68 + cl]     = acc[mt][nt][2];
            lg[(r0i + 8) * 68 + cl + 1] = acc[mt][nt][3];
        }
    }
    __syncthreads();

    if (t < 128) {
        int r = rows[t];
        if (r >= 0) {
            float v[64];
            float mx = -3.4e38f;
#pragma unroll
            for (int j = 0; j < 64; j++) {
                v[j] = lg[t * 68 + j] + b2s[j];
                mx = fmaxf(mx, v[j]);
            }
            float s = 0.f;
#pragma unroll
            for (int j = 0; j < 64; j++) {
                v[j] = __expf(v[j] - mx);
                s += v[j];
            }
            float inv = 1.0f / s;
            float4* op = (float4*)(out + (size_t)r * NCLS);
#pragma unroll
            for (int q = 0; q < 16; q++)
                op[q] = make_float4(v[4 * q] * inv, v[4 * q + 1] * inv,
                                    v[4 * q + 2] * inv, v[4 * q + 3] * inv);
        }
    }
#undef L2_ISSUE
}

// ---------------------------------------------------------------------------
extern "C" void kernel_launch(void* const* d_in, const int* in_sizes, int n_in,
                              void* d_out, int out_size)
{
    const int*   domain = (const int*)  d_in[0];
    const float* x      = (const float*)d_in[1];
    const float* W1     = (const float*)d_in[2];
    const float* b1     = (const float*)d_in[3];
    const float* W2     = (const float*)d_in[4];
    const float* b2     = (const float*)d_in[5];
    float* out = (float*)d_out;

    cudaFuncSetAttribute(k_gemm1, cudaFuncAttributeMaxDynamicSharedMemorySize, L1_SMEM);
    cudaFuncSetAttribute(k_gemm2, cudaFuncAttributeMaxDynamicSharedMemorySize, L2_SMEM);

    k_convX<<<(BATCH * FDIM1 / 8) / 256, 256>>>(x);           // + counter reset
    k_bucket<<<BATCH / 256, 256>>>(domain);
    k_convW<<<dim3(32, 18, N_EXPERTS), dim3(32, 8)>>>(W1, W2);
    k_gemm1<<<dim3(BATCH / 128, FDIM2 / 128, N_EXPERTS), 256, L1_SMEM>>>(b1);
    k_gemm2<<<dim3(BATCH / 128, N_EXPERTS), 256, L2_SMEM>>>(b2, out);
}